// round 1
// baseline (speedup 1.0000x reference)
#include <cuda_runtime.h>
#include <cuda_bf16.h>

#define N_ROWS      262144
#define NUM_CLASSES 80
#define K_ROWS      131072      // int(N * 0.5)
#define CONF        0.25f

// Scratch (allocation-free): per-row scores + first-below-threshold index.
__device__ float g_scores[K_ROWS];
__device__ int   g_first_bad;

// ---------------------------------------------------------------------------
// 0) init: reset the atomicMin target and zero the output scalar.
// ---------------------------------------------------------------------------
__global__ void init_kernel(float* __restrict__ out) {
    g_first_bad = K_ROWS;
    out[0] = 0.0f;
}

// ---------------------------------------------------------------------------
// 1) score: one warp per row. Coalesced reads of the 80-float row,
//    warp shfl max-reduce, store score, atomicMin on first below-CONF row.
// ---------------------------------------------------------------------------
__global__ void score_kernel(const float* __restrict__ post) {
    const int warp = (blockIdx.x * blockDim.x + threadIdx.x) >> 5;
    const int lane = threadIdx.x & 31;
    if (warp >= K_ROWS) return;

    const float* row = post + (size_t)warp * NUM_CLASSES;

    // 80 = 32 + 32 + 16 elements; each segment is a coalesced warp load.
    float m = row[lane];
    m = fmaxf(m, row[lane + 32]);
    if (lane < 16) m = fmaxf(m, row[lane + 64]);

    #pragma unroll
    for (int o = 16; o > 0; o >>= 1)
        m = fmaxf(m, __shfl_xor_sync(0xFFFFFFFFu, m, o));

    if (lane == 0) {
        g_scores[warp] = m;
        if (m < CONF) atomicMin(&g_first_bad, warp);
    }
}

// ---------------------------------------------------------------------------
// 2) sum: grid-stride sum of g_scores[0 : g_first_bad], block reduce,
//    atomicAdd into the scalar output.
// ---------------------------------------------------------------------------
__global__ void sum_kernel(float* __restrict__ out) {
    const int fb = g_first_bad;   // finalized by previous launch
    float s = 0.0f;

    for (int i = blockIdx.x * blockDim.x + threadIdx.x; i < fb;
         i += gridDim.x * blockDim.x)
        s += g_scores[i];

    // warp reduce
    #pragma unroll
    for (int o = 16; o > 0; o >>= 1)
        s += __shfl_xor_sync(0xFFFFFFFFu, s, o);

    __shared__ float red[32];
    const int lane = threadIdx.x & 31;
    const int wid  = threadIdx.x >> 5;
    if (lane == 0) red[wid] = s;
    __syncthreads();

    if (wid == 0) {
        const int nwarps = blockDim.x >> 5;
        s = (lane < nwarps) ? red[lane] : 0.0f;
        #pragma unroll
        for (int o = 16; o > 0; o >>= 1)
            s += __shfl_xor_sync(0xFFFFFFFFu, s, o);
        if (lane == 0) atomicAdd(out, s);
    }
}

// ---------------------------------------------------------------------------
// launch
// ---------------------------------------------------------------------------
extern "C" void kernel_launch(void* const* d_in, const int* in_sizes, int n_in,
                              void* d_out, int out_size) {
    const float* post = (const float*)d_in[0];   // [N_ROWS, NUM_CLASSES] fp32
    float* out = (float*)d_out;                  // scalar fp32

    init_kernel<<<1, 1>>>(out);

    // one warp per row: K_ROWS warps, 256 threads/block = 8 warps/block
    const int threads = 256;
    const int blocks  = (K_ROWS * 32) / threads;   // 16384
    score_kernel<<<blocks, threads>>>(post);

    sum_kernel<<<148, 256>>>(out);
}

// round 2
// speedup vs baseline: 1.1543x; 1.1543x over previous
#include <cuda_runtime.h>
#include <cuda_bf16.h>

#define N_ROWS       262144
#define NUM_CLASSES  80
#define K_ROWS       131072        // int(N * 0.5)
#define CONF         0.25f

#define ROWS_PER_BLK 64
#define NBLOCKS      (K_ROWS / ROWS_PER_BLK)   // 2048
#define THREADS      256                        // 8 warps -> 8 rows each

// Per-block scratch (16 KB total): local first-bad index and prefix sum.
__device__ int   g_bad [NBLOCKS];
__device__ float g_psum[NBLOCKS];

// ---------------------------------------------------------------------------
// 1) score: each block owns 64 consecutive rows. One warp per row (8 rows per
//    warp via float4 loads on 20 lanes). Scores land in smem; the block then
//    finds its local first-below-CONF row and the sum of scores before it.
// ---------------------------------------------------------------------------
__global__ __launch_bounds__(THREADS) void score_kernel(const float* __restrict__ post) {
    __shared__ float ssc[ROWS_PER_BLK];
    __shared__ int   sbad;
    __shared__ float sred[THREADS / 32];

    const int tid  = threadIdx.x;
    const int lane = tid & 31;
    const int warp = tid >> 5;                      // 0..7

    if (tid == 0) sbad = ROWS_PER_BLK;

    const int rowBase = blockIdx.x * ROWS_PER_BLK + warp * 8;

    // 8 independent rows per warp: 8 front-batched LDG.128 for MLP.
    #pragma unroll
    for (int i = 0; i < 8; i++) {
        const int row = rowBase + i;
        float m = -1e30f;
        if (lane < 20) {
            const float4 v = __ldg((const float4*)(post + (size_t)row * NUM_CLASSES) + lane);
            m = fmaxf(fmaxf(v.x, v.y), fmaxf(v.z, v.w));
        }
        #pragma unroll
        for (int o = 16; o > 0; o >>= 1)
            m = fmaxf(m, __shfl_xor_sync(0xFFFFFFFFu, m, o));
        if (lane == 0) ssc[warp * 8 + i] = m;
    }
    __syncthreads();   // scores visible; sbad initialized

    // local first-bad
    if (tid < ROWS_PER_BLK && ssc[tid] < CONF)
        atomicMin(&sbad, tid);
    __syncthreads();
    const int bad = sbad;

    // prefix sum of scores before local bad (0 for threads outside range)
    float s = (tid < ROWS_PER_BLK && tid < bad) ? ssc[tid] : 0.0f;
    #pragma unroll
    for (int o = 16; o > 0; o >>= 1)
        s += __shfl_xor_sync(0xFFFFFFFFu, s, o);
    if (lane == 0) sred[warp] = s;
    __syncthreads();
    if (warp == 0) {
        s = (lane < THREADS / 32) ? sred[lane] : 0.0f;
        #pragma unroll
        for (int o = 4; o > 0; o >>= 1)
            s += __shfl_xor_sync(0xFFFFFFFFu, s, o);
        if (lane == 0) {
            g_bad [blockIdx.x] = bad;
            g_psum[blockIdx.x] = s;
        }
    }
}

// ---------------------------------------------------------------------------
// 2) finalize: one block. Find first block b* with local bad < 64, then
//    sum psum[b] for b <= b* (blocks before b* have psum == full sum).
// ---------------------------------------------------------------------------
__global__ __launch_bounds__(256) void finalize_kernel(float* __restrict__ out) {
    __shared__ int   ired[8];
    __shared__ float fred[8];

    const int tid  = threadIdx.x;
    const int lane = tid & 31;
    const int warp = tid >> 5;

    // first bad block
    int bstar = NBLOCKS;   // sentinel: no bad anywhere -> include all blocks
    for (int b = tid; b < NBLOCKS; b += 256)
        if (g_bad[b] < ROWS_PER_BLK) bstar = min(bstar, b);
    #pragma unroll
    for (int o = 16; o > 0; o >>= 1)
        bstar = min(bstar, __shfl_xor_sync(0xFFFFFFFFu, bstar, o));
    if (lane == 0) ired[warp] = bstar;
    __syncthreads();
    if (tid < 8) bstar = ired[tid];
    if (warp == 0) {
        #pragma unroll
        for (int o = 4; o > 0; o >>= 1)
            bstar = min(bstar, __shfl_xor_sync(0xFFFFFFFFu, bstar, o));
    }
    if (tid == 0) ired[0] = bstar;
    __syncthreads();
    bstar = ired[0];

    // sum psum over b <= bstar (bstar==NBLOCKS means all)
    const int last = (bstar < NBLOCKS) ? bstar : (NBLOCKS - 1);
    float s = 0.0f;
    for (int b = tid; b <= last; b += 256)
        s += g_psum[b];
    #pragma unroll
    for (int o = 16; o > 0; o >>= 1)
        s += __shfl_xor_sync(0xFFFFFFFFu, s, o);
    if (lane == 0) fred[warp] = s;
    __syncthreads();
    if (warp == 0) {
        s = (lane < 8) ? fred[lane] : 0.0f;
        #pragma unroll
        for (int o = 4; o > 0; o >>= 1)
            s += __shfl_xor_sync(0xFFFFFFFFu, s, o);
        if (lane == 0) out[0] = s;
    }
}

// ---------------------------------------------------------------------------
extern "C" void kernel_launch(void* const* d_in, const int* in_sizes, int n_in,
                              void* d_out, int out_size) {
    const float* post = (const float*)d_in[0];   // [N_ROWS, NUM_CLASSES] fp32
    float* out = (float*)d_out;                  // scalar fp32

    score_kernel<<<NBLOCKS, THREADS>>>(post);
    finalize_kernel<<<1, 256>>>(out);
}